// round 4
// baseline (speedup 1.0000x reference)
#include <cuda_runtime.h>
#include <math.h>

#define NN 8
#define LAGI 5
#define POLI 3
#define NSI 2

__global__ void __launch_bounds__(128)
fleigh_kernel(const float* __restrict__ Aall, float* __restrict__ out, int B)
{
    int b = blockIdx.x * blockDim.x + threadIdx.x;
    if (b >= B) return;
    const float* Ap = Aall + (size_t)b * 64;

    // ---- load A; f32 norm (non-FMA, matching XLA square->reduce) ----
    float Af[64];
    float nrm2 = 0.f;
    #pragma unroll
    for (int i = 0; i < 64; i++) {
        float v = Ap[i];
        Af[i] = v;
        nrm2 = __fadd_rn(nrm2, __fmul_rn(v, v));
    }
    float nrmf = sqrtf(nrm2);
    // scale promotes to f64 in the reference (np.sqrt(8) is strong float64)
    double scale = (double)nrmf / 2.8284271247461903;
    scale = fmax(scale, 1e-12);
    // As is f64: f32 A divided by f64 scale
    double As[64];
    #pragma unroll
    for (int i = 0; i < 64; i++) As[i] = (double)Af[i] / scale;

    // ---- Faddeev-LeVerrier (f64): c coeffs + M_2..M_8 stored ----
    double c[9];
    #pragma unroll
    for (int i = 0; i < 9; i++) c[i] = 0.0;
    c[8] = 1.0;
    {   // k = 1: M1 = I, c[7] = -trace
        double tr = 0.0;
        #pragma unroll
        for (int i = 0; i < 8; i++) tr += As[i * 8 + i];
        c[7] = -tr;
    }
    double Mst[7 * 64];   // Mst[(k-2)*64 + ...] = M_k, k=2..8
    {   // k = 2: M2 = As + c[7] I
        double tr = 0.0;
        #pragma unroll
        for (int i = 0; i < 8; i++) {
            #pragma unroll
            for (int j = 0; j < 8; j++) {
                double v = As[i * 8 + j] + ((i == j) ? c[7] : 0.0);
                Mst[i * 8 + j] = v;
                tr += As[i * 8 + j] * v;
            }
        }
        c[6] = -tr / 2.0;
    }
    #pragma unroll 1
    for (int k = 3; k <= 8; k++) {
        const double* prev = Mst + (k - 3) * 64;
        double* curm = Mst + (k - 2) * 64;
        double ck = c[9 - k];
        double tr = 0.0;
        #pragma unroll 1
        for (int i = 0; i < 8; i++) {
            double ai[8];
            #pragma unroll
            for (int t = 0; t < 8; t++) ai[t] = As[i * 8 + t];
            #pragma unroll
            for (int j = 0; j < 8; j++) {
                double s = (i == j) ? ck : 0.0;
                #pragma unroll
                for (int t = 0; t < 8; t++) s += ai[t] * prev[t * 8 + j];
                curm[i * 8 + j] = s;
                tr += As[i * 8 + j] * s;
            }
        }
        c[8 - k] = -tr / (double)k;
    }

    // ---- initial guesses: sorted diagonal + linspace perturbation ----
    double zi[8];
    #pragma unroll
    for (int i = 0; i < 8; i++) zi[i] = As[i * 8 + i];
    #pragma unroll 1
    for (int i = 1; i < 8; i++) {           // insertion sort ascending
        double key = zi[i];
        int j = i - 1;
        while (j >= 0 && zi[j] > key) { zi[j + 1] = zi[j]; j--; }
        zi[j + 1] = key;
    }
    const double lstep = 2e-4 / 7.0;

    // ---- Laguerre with deflation (f64, NON-FMA to match XLA elementwise) ----
    double cl[9];
    #pragma unroll
    for (int i = 0; i < 9; i++) cl[i] = c[i];
    double roots[8];
    float fric[8], sett[8];
    #pragma unroll 1
    for (int ri = 0; ri < 8; ri++) {
        int deg = 8 - ri;
        double dd = (double)deg;
        double z = __dadd_rn(zi[ri], __dadd_rn(-1e-4, __dmul_rn(lstep, (double)ri)));
        float fr = 0.f, st = (float)LAGI;
        #pragma unroll 1
        for (int it = 0; it < LAGI; it++) {
            double pv = cl[deg], dp = 0.0, d2 = 0.0;
            #pragma unroll 1
            for (int j = deg - 1; j >= 0; j--) {
                d2 = __dadd_rn(__dmul_rn(d2, z), dp);
                dp = __dadd_rn(__dmul_rn(dp, z), pv);
                pv = __dadd_rn(__dmul_rn(pv, z), cl[j]);
            }
            float dp_abs = (float)fabs(dp);
            fr = __fadd_rn(fr, 1.0f / __fadd_rn(dp_abs, 1e-8f));
            float pv_abs = (float)fabs(pv);
            if (pv_abs < 1e-6f && st == (float)LAGI) st = (float)it;
            bool ok = fabs(pv) > 1e-30;
            double ps = ok ? pv : 1.0;
            double G = ok ? (dp / ps) : 0.0;
            double GG = __dmul_rn(G, G);
            double twod2 = ok ? (__dmul_rn(2.0, d2) / ps) : 0.0;
            double H = __dadd_rn(GG, -twod2);
            double inner = __dadd_rn(__dmul_rn(dd, H), -GG);
            double disc = __dmul_rn(__dadd_rn(dd, -1.0), inner);
            disc = disc > 0.0 ? disc : 0.0;
            double sq = sqrt(disc);
            double gp = __dadd_rn(G, sq), gm = __dadd_rn(G, -sq);
            double den = (fabs(gp) >= fabs(gm)) ? gp : gm;
            bool dok = fabs(den) > 1e-20;
            double ds = dok ? den : 1.0;
            z = __dadd_rn(z, -(dok ? (dd / ds) : 0.0));
        }
        roots[ri] = z; fric[ri] = fr; sett[ri] = st;
        // synthetic-division deflation (non-FMA)
        double bcur = cl[deg];
        #pragma unroll 1
        for (int j = deg - 1; j >= 1; j--) {
            double tmp = cl[j];
            cl[j] = bcur;
            bcur = __dadd_rn(tmp, __dmul_rn(z, bcur));
        }
        cl[0] = bcur;
    }

    // ---- Newton polish on full monic char poly (f64, NON-FMA) ----
    #pragma unroll 1
    for (int p = 0; p < POLI; p++) {
        #pragma unroll 1
        for (int i = 0; i < 8; i++) {
            double r = roots[i];
            double pv = 1.0, dp = 0.0;
            #pragma unroll
            for (int j = 7; j >= 0; j--) {
                dp = __dadd_rn(__dmul_rn(dp, r), pv);
                pv = __dadd_rn(__dmul_rn(pv, r), c[j]);
            }
            if (fabs(dp) > 1e-30) r = __dadd_rn(r, -(pv / dp));
            roots[i] = r;
        }
    }

    // ---- adjugate via Horner over M_k: column norms, best column, eigenvector ----
    double cn2[64];   // [lam i][col]
    #pragma unroll
    for (int e = 0; e < 64; e++) cn2[e] = 0.0;
    #pragma unroll 1
    for (int a = 0; a < 8; a++) {
        #pragma unroll 1
        for (int col = 0; col < 8; col++) {
            double m1 = (a == col) ? 1.0 : 0.0;
            double mv0 = Mst[0 * 64 + a * 8 + col];
            double mv1 = Mst[1 * 64 + a * 8 + col];
            double mv2 = Mst[2 * 64 + a * 8 + col];
            double mv3 = Mst[3 * 64 + a * 8 + col];
            double mv4 = Mst[4 * 64 + a * 8 + col];
            double mv5 = Mst[5 * 64 + a * 8 + col];
            double mv6 = Mst[6 * 64 + a * 8 + col];
            #pragma unroll
            for (int i = 0; i < 8; i++) {
                double lam = roots[i];
                double r = m1;
                r = r * lam + mv0;
                r = r * lam + mv1;
                r = r * lam + mv2;
                r = r * lam + mv3;
                r = r * lam + mv4;
                r = r * lam + mv5;
                r = r * lam + mv6;
                cn2[i * 8 + col] += r * r;
            }
        }
    }
    float V[64];   // V[a*8 + i]  (component a, eigenvector i)
    #pragma unroll 1
    for (int i = 0; i < 8; i++) {
        int best = 0;
        double bv = cn2[i * 8 + 0];
        #pragma unroll
        for (int col = 1; col < 8; col++) {
            double v = cn2[i * 8 + col];
            if (v > bv) { bv = v; best = col; }
        }
        double lam = roots[i];
        double vec[8];
        double s2 = 0.0;
        #pragma unroll 1
        for (int a = 0; a < 8; a++) {
            double r = (a == best) ? 1.0 : 0.0;
            #pragma unroll
            for (int k = 0; k < 7; k++) r = r * lam + Mst[k * 64 + a * 8 + best];
            vec[a] = r;
            s2 += r * r;
        }
        double nrm = sqrt(s2) + 1e-30;
        #pragma unroll
        for (int a = 0; a < 8; a++) V[a * 8 + i] = (float)(vec[a] / nrm);
    }

    // ---- Newton-Schulz orthogonalization (f32) ----
    float Y[64], X[64];
    #pragma unroll 1
    for (int i = 0; i < 8; i++) {
        #pragma unroll
        for (int j = 0; j < 8; j++) {
            float s = 0.f;
            #pragma unroll
            for (int a = 0; a < 8; a++) s += V[a * 8 + i] * V[a * 8 + j];
            Y[i * 8 + j] = s;
            X[i * 8 + j] = (i == j) ? 1.f : 0.f;
        }
    }
    #pragma unroll 1
    for (int ns = 0; ns < NSI; ns++) {
        float T[64], Xn[64], Yn[64];
        #pragma unroll
        for (int i = 0; i < 8; i++)
            #pragma unroll
            for (int j = 0; j < 8; j++)
                T[i * 8 + j] = ((i == j) ? 3.f : 0.f) - Y[i * 8 + j];
        #pragma unroll 1
        for (int i = 0; i < 8; i++) {
            #pragma unroll
            for (int j = 0; j < 8; j++) {
                float sx = 0.f, sy = 0.f;
                #pragma unroll
                for (int k = 0; k < 8; k++) {
                    sx += X[i * 8 + k] * T[k * 8 + j];
                    sy += T[i * 8 + k] * Y[k * 8 + j];
                }
                Xn[i * 8 + j] = 0.5f * sx;
                Yn[i * 8 + j] = 0.5f * sy;
            }
        }
        #pragma unroll
        for (int e = 0; e < 64; e++) { X[e] = Xn[e]; Y[e] = Yn[e]; }
    }
    {   // V = V @ X
        float Vn[64];
        #pragma unroll 1
        for (int a = 0; a < 8; a++) {
            #pragma unroll
            for (int i = 0; i < 8; i++) {
                float s = 0.f;
                #pragma unroll
                for (int k = 0; k < 8; k++) s += V[a * 8 + k] * X[k * 8 + i];
                Vn[a * 8 + i] = s;
            }
        }
        #pragma unroll
        for (int e = 0; e < 64; e++) V[e] = Vn[e];
    }

    // ---- refinement residual ----
    float rr2 = 0.f;
    #pragma unroll 1
    for (int i = 0; i < 8; i++) {
        #pragma unroll
        for (int j = 0; j < 8; j++) {
            float s = 0.f;
            #pragma unroll
            for (int a = 0; a < 8; a++) s += V[a * 8 + i] * V[a * 8 + j];
            float d = s - ((i == j) ? 1.f : 0.f);
            rr2 += d * d;
        }
    }
    float rr = sqrtf(rr2);

    // ---- evals = diag(V^T A V) with ORIGINAL A (f32) ----
    float evals[8];
    #pragma unroll 1
    for (int i = 0; i < 8; i++) {
        float e = 0.f;
        #pragma unroll
        for (int a = 0; a < 8; a++) {
            float av = 0.f;
            #pragma unroll
            for (int k = 0; k < 8; k++) av += Af[a * 8 + k] * V[k * 8 + i];
            e += V[a * 8 + i] * av;
        }
        evals[i] = e;
    }

    // ---- stable argsort ascending ----
    int perm[8];
    #pragma unroll
    for (int i = 0; i < 8; i++) perm[i] = i;
    #pragma unroll 1
    for (int i = 1; i < 8; i++) {
        int key = perm[i];
        float kv = evals[key];
        int j = i - 1;
        while (j >= 0 && evals[perm[j]] > kv) { perm[j + 1] = perm[j]; j--; }
        perm[j + 1] = key;
    }

    // ---- outputs (concatenated, f32) ----
    size_t Bs = (size_t)B;
    float* o_se = out;
    float* o_sv = out + Bs * 8;
    float* o_cc = out + Bs * 72;
    float* o_fr = out + Bs * 80;
    float* o_st = out + Bs * 88;
    float* o_eo = out + Bs * 96;
    float* o_rr = out + Bs * 104;

    #pragma unroll 1
    for (int i = 0; i < 8; i++) {
        int p = perm[i];
        o_se[(size_t)b * 8 + i] = evals[p];
        o_cc[(size_t)b * 8 + i] = (float)c[i];
        o_fr[(size_t)b * 8 + i] = fric[p];
        o_st[(size_t)b * 8 + i] = sett[p];
        o_eo[(size_t)b * 8 + i] = (float)i;
    }
    #pragma unroll 1
    for (int i = 0; i < 8; i++) {
        int p = perm[i];
        int ma = 0;
        float mv = fabsf(V[0 * 8 + p]);
        #pragma unroll
        for (int a = 1; a < 8; a++) {
            float v = fabsf(V[a * 8 + p]);
            if (v > mv) { mv = v; ma = a; }
        }
        float sg = V[ma * 8 + p];
        sg = (sg > 0.f) ? 1.f : ((sg < 0.f) ? -1.f : 0.f);
        #pragma unroll
        for (int a = 0; a < 8; a++)
            o_sv[(size_t)b * 64 + a * 8 + i] = V[a * 8 + p] * sg;
    }
    o_rr[b] = rr;
}

extern "C" void kernel_launch(void* const* d_in, const int* in_sizes, int n_in,
                              void* d_out, int out_size)
{
    const float* A = (const float*)d_in[0];
    float* out = (float*)d_out;
    int B = in_sizes[0] / 64;
    int threads = 128;
    int blocks = (B + threads - 1) / threads;
    fleigh_kernel<<<blocks, threads>>>(A, out, B);
}